// round 8
// baseline (speedup 1.0000x reference)
#include <cuda_runtime.h>

#define H   128
#define FF  8
#define C4  512
#define MB  14     // batch rows per CTA
#define NT  384    // 3 k-groups x 128
#define BB  2048
#define HS  20     // hsm row stride (floats): 4-way store conflict, 16B-aligned rows

// U blocked as UG[k][j][gate] (float4 per (k,j)): coalesced LDG.128.
__device__ __align__(16) float g_UGe[H * C4];
__device__ __align__(16) float g_UGd[H * C4];

typedef unsigned long long u64;

__device__ __forceinline__ u64 dup2(float v) {
    u64 r; asm("mov.b64 %0, {%1, %1};" : "=l"(r) : "f"(v)); return r;
}
__device__ __forceinline__ u64 pack2(float lo, float hi) {
    u64 r; asm("mov.b64 %0, {%1, %2};" : "=l"(r) : "f"(lo), "f"(hi)); return r;
}
__device__ __forceinline__ void fma2(u64& d, u64 a, u64 b) {
    asm("fma.rn.f32x2 %0, %1, %2, %0;" : "+l"(d) : "l"(a), "l"(b));
}
__device__ __forceinline__ void add2(u64& d, u64 a) {
    asm("add.rn.f32x2 %0, %0, %1;" : "+l"(d) : "l"(a));
}
__device__ __forceinline__ void unpack2(u64 v, float& lo, float& hi) {
    asm("mov.b64 {%0, %1}, %2;" : "=f"(lo), "=f"(hi) : "l"(v));
}
__device__ __forceinline__ float ex2f(float x){ float r; asm("ex2.approx.f32 %0, %1;" : "=f"(r) : "f"(x)); return r; }
__device__ __forceinline__ float rcpf(float x){ float r; asm("rcp.approx.f32 %0, %1;" : "=f"(r) : "f"(x)); return r; }
__device__ __forceinline__ float sigm(float x){ return rcpf(1.f + ex2f(-1.4426950408889634f * x)); }
__device__ __forceinline__ float tanhf_(float x){ return fmaf(-2.f, rcpf(1.f + ex2f(2.8853900817779268f * x)), 1.f); }

#define BARSYNC() asm volatile("bar.sync 0;" ::: "memory")

__device__ __forceinline__ constexpr int keeper(int p) { return p < 2 ? 0 : (p < 4 ? 1 : 2); }

// 7 row-pairs from a stride-HS row (base 16B-aligned): 3x LDS.128 + 1x LDS.64
__device__ __forceinline__ void load_pairs7(u64* hp, const float* row) {
    ulonglong2 a = *(const ulonglong2*)(row);
    ulonglong2 b = *(const ulonglong2*)(row + 4);
    ulonglong2 c = *(const ulonglong2*)(row + 8);
    hp[0] = a.x; hp[1] = a.y; hp[2] = b.x; hp[3] = b.y;
    hp[4] = c.x; hp[5] = c.y;
    hp[6] = *(const u64*)(row + 12);
}

__global__ void transposeU_kernel(const float* __restrict__ Ue, const float* __restrict__ Ud) {
    int i = blockIdx.x * blockDim.x + threadIdx.x;
    if (i < H * C4) {
        int k = i / C4, c = i % C4;
        int o = (k * H + (c & 127)) * 4 + (c >> 7);
        g_UGe[o] = Ue[i];
        g_UGd[o] = Ud[i];
    }
}

// dyn smem (floats): hsm[2][128][HS] | xsm[2][8][16] | wsm[4096] | wosm[1024] | zex2(u64x2 x 3584)
#define SM_H   0
#define SM_X   5120
#define SM_W   5376
#define SM_WO  9472
#define SM_ZX  10496
#define SM_FLOATS (SM_ZX + 14336)

// Group G: k in [KK0, KK0+KN). Kept pairs [P0, P0+NPk) get bias + x@W folded
// locally; all other pairs' h@U partials cross via zex2 (2 gates per u64x2).
template<int G>
__device__ __forceinline__ void lstm_body(
    int tid, int rs, int T,
    const float* __restrict__ x,
    const float* __restrict__ We, const float* __restrict__ be,
    const float* __restrict__ Wd, const float* __restrict__ bd,
    const float* __restrict__ bog,
    float* __restrict__ out,
    float* hsm, float* xsm, float* wsm, const float* wosm, ulonglong2* zex2)
{
    constexpr int KK0 = (G == 0) ? 0 : ((G == 1) ? 44 : 88);
    constexpr int KN  = (G == 2) ? 40 : 44;
    constexpr int P0  = (G == 0) ? 0 : ((G == 1) ? 2 : 4);
    constexpr int NPk = (G == 2) ? 3 : 2;

    const int j = tid & (H - 1);
    const int  xm = tid >> 3, xf = tid & 7;
    const bool xth = tid < MB * FF;                  // within G0's threads only
    const bool gx  = xth && (rs + xm < BB);
    const float bof = bog[xf];
    const float* xrow = x   + (size_t)(rs + xm) * T * FF + xf;
    float*       orow = out + (size_t)(rs + xm) * T * FF + xf;

    float cst[2 * NPk];
    #pragma unroll
    for (int i = 0; i < 2 * NPk; i++) cst[i] = 0.f;

    int buf = 0;

    for (int phase = 0; phase < 2; phase++) {
        const bool dec = (phase == 1);
        const float4* UG4 = ((const float4*)(dec ? g_UGd : g_UGe)) + j;
        const float*  Wm  = dec ? Wd : We;
        const float*  bv  = dec ? bd : be;

        for (int i = tid; i < FF * C4; i += NT) {    // stage W [f][j][g]
            int f = i >> 9, c = i & 511;
            wsm[(f * H + (c & 127)) * 4 + (c >> 7)] = Wm[i];
        }
        u64 bdv[4];
        #pragma unroll
        for (int g = 0; g < 4; g++) bdv[g] = dup2(bv[g * H + j]);
        BARSYNC();

        for (int t = 0; t < T; t++) {
            const int nbuf = buf ^ 1;
            const float* hbuf = hsm + buf  * (H * HS);
            float*       hnew = hsm + nbuf * (H * HS);
            const float* xbuf = xsm + buf  * 128;

            u64 acc[4][7];
            #pragma unroll
            for (int g = 0; g < 4; g++)
                #pragma unroll
                for (int p = 0; p < 7; p++)
                    acc[g][p] = (p >= P0 && p < P0 + NPk) ? bdv[g] : 0ull;

            // x @ W for kept pairs only
            #pragma unroll
            for (int f = 0; f < FF; f++) {
                float4 wf4 = ((const float4*)wsm)[f * H + j];
                u64 xp[NPk];
                #pragma unroll
                for (int pi = 0; pi < NPk; pi++)
                    xp[pi] = *(const u64*)(xbuf + f * 16 + 2 * (P0 + pi));
                #pragma unroll
                for (int g = 0; g < 4; g++) {
                    u64 wd = dup2(((const float*)&wf4)[g]);
                    #pragma unroll
                    for (int pi = 0; pi < NPk; pi++) fma2(acc[g][P0 + pi], xp[pi], wd);
                }
            }

            // h @ U over this group's k-range; one 4-k block prefetched ahead
            float4 uc[4], un[4];
            #pragma unroll
            for (int q = 0; q < 4; q++) uc[q] = UG4[(KK0 + q) << 7];
            for (int kb = 0; kb < KN; kb += 4) {
                const int kn = (kb + 4 < KN) ? kb + 4 : 0;
                #pragma unroll
                for (int q = 0; q < 4; q++) un[q] = UG4[(KK0 + kn + q) << 7];
                #pragma unroll
                for (int q = 0; q < 4; q++) {
                    u64 hp[7];
                    load_pairs7(hp, hbuf + (KK0 + kb + q) * HS);
                    #pragma unroll
                    for (int g = 0; g < 4; g++) {
                        u64 d = dup2(((const float*)&uc[q])[g]);
                        #pragma unroll
                        for (int p = 0; p < 7; p++) fma2(acc[g][p], hp[p], d);
                    }
                }
                #pragma unroll
                for (int q = 0; q < 4; q++) uc[q] = un[q];
            }

            // cross non-kept partials (2 gates per STS.128, lane-consecutive j)
            #pragma unroll
            for (int p = 0; p < 7; p++) {
                if (keeper(p) == G) continue;
                const int slot = (G < keeper(p)) ? G : G - 1;
                #pragma unroll
                for (int g2 = 0; g2 < 2; g2++) {
                    ulonglong2 v;
                    v.x = acc[2 * g2][p];
                    v.y = acc[2 * g2 + 1][p];
                    zex2[((g2 * 7 + p) * 2 + slot) * H + j] = v;
                }
            }
            BARSYNC();

            // gather + gates for kept pairs; write h into the other buffer
            u64* hrow = (u64*)(hnew + j * HS);
            #pragma unroll
            for (int pi = 0; pi < NPk; pi++) {
                const int p = P0 + pi;
                #pragma unroll
                for (int g2 = 0; g2 < 2; g2++) {
                    ulonglong2 e0 = zex2[((g2 * 7 + p) * 2 + 0) * H + j];
                    ulonglong2 e1 = zex2[((g2 * 7 + p) * 2 + 1) * H + j];
                    add2(acc[2 * g2][p],     e0.x); add2(acc[2 * g2][p],     e1.x);
                    add2(acc[2 * g2 + 1][p], e0.y); add2(acc[2 * g2 + 1][p], e1.y);
                }
                float zi0, zi1, zf0, zf1, zg0, zg1, zo0, zo1;
                unpack2(acc[0][p], zi0, zi1);
                unpack2(acc[1][p], zf0, zf1);
                unpack2(acc[2][p], zg0, zg1);
                unpack2(acc[3][p], zo0, zo1);
                float c0 = fmaf(sigm(zf0), cst[2*pi    ], sigm(zi0) * tanhf_(zg0));
                float c1 = fmaf(sigm(zf1), cst[2*pi + 1], sigm(zi1) * tanhf_(zg1));
                cst[2*pi    ] = c0;
                cst[2*pi + 1] = c1;
                hrow[p] = pack2(sigm(zo0) * tanhf_(c0), sigm(zo1) * tanhf_(c1));
            }

            if (!dec) {
                if (G == 0 && gx) {         // prefetch next x; clamp keeps x[:,T-1,:]
                    int tn = (t + 1 < T) ? (t + 1) : (T - 1);
                    (xsm + nbuf * 128)[xf * 16 + xm] = xrow[(size_t)tn * FF];
                }
                BARSYNC();                  // h(nbuf) + x(nbuf) ready
            } else {
                BARSYNC();                  // h(nbuf) complete
                if (xth) {
                    float a = 0.f, b2 = 0.f, c2 = 0.f, d2 = 0.f;
                    #pragma unroll 8
                    for (int k = 0; k < H; k += 4) {
                        a  = fmaf(hnew[(k    ) * HS + xm], wosm[(k    ) * FF + xf], a);
                        b2 = fmaf(hnew[(k + 1) * HS + xm], wosm[(k + 1) * FF + xf], b2);
                        c2 = fmaf(hnew[(k + 2) * HS + xm], wosm[(k + 2) * FF + xf], c2);
                        d2 = fmaf(hnew[(k + 3) * HS + xm], wosm[(k + 3) * FF + xf], d2);
                    }
                    float y = fmaxf(bof + ((a + b2) + (c2 + d2)), 0.f);
                    (xsm + nbuf * 128)[xf * 16 + xm] = y;
                    if (gx) orow[(size_t)t * FF] = y;
                }
                BARSYNC();                  // y feedback visible
            }
            buf = nbuf;
        }
    }
}

__global__ void __launch_bounds__(NT, 1)
lstm_ae_kernel(const float* __restrict__ x,
               const float* __restrict__ We, const float* __restrict__ be,
               const float* __restrict__ Wd, const float* __restrict__ bd,
               const float* __restrict__ Wo, const float* __restrict__ bog,
               float* __restrict__ out, int T)
{
    extern __shared__ __align__(16) float sm[];
    float*       hsm  = sm + SM_H;
    float*       xsm  = sm + SM_X;
    float*       wsm  = sm + SM_W;
    float*       wosm = sm + SM_WO;
    ulonglong2*  zex2 = (ulonglong2*)(sm + SM_ZX);

    const int tid = threadIdx.x;
    const int rs  = blockIdx.x * MB;

    for (int i = tid; i < SM_W; i += NT) sm[i] = 0.f;       // hsm + xsm
    for (int i = tid; i < H * FF; i += NT) wosm[i] = Wo[i];
    {
        const int xm = tid >> 3, xf = tid & 7;
        if (tid < MB * FF && rs + xm < BB)
            xsm[xf * 16 + xm] = x[(size_t)(rs + xm) * T * FF + xf];
    }
    __syncthreads();

    if (tid < 128)
        lstm_body<0>(tid, rs, T, x, We, be, Wd, bd, bog, out, hsm, xsm, wsm, wosm, zex2);
    else if (tid < 256)
        lstm_body<1>(tid, rs, T, x, We, be, Wd, bd, bog, out, hsm, xsm, wsm, wosm, zex2);
    else
        lstm_body<2>(tid, rs, T, x, We, be, Wd, bd, bog, out, hsm, xsm, wsm, wosm, zex2);
}

extern "C" void kernel_launch(void* const* d_in, const int* in_sizes, int n_in,
                              void* d_out, int out_size)
{
    const float* x  = (const float*)d_in[0];
    const float* We = (const float*)d_in[1];
    const float* Ue = (const float*)d_in[2];
    const float* be = (const float*)d_in[3];
    const float* Wd = (const float*)d_in[4];
    const float* Ud = (const float*)d_in[5];
    const float* bd = (const float*)d_in[6];
    const float* Wo = (const float*)d_in[7];
    const float* bo = (const float*)d_in[8];
    float* out = (float*)d_out;

    const int T = in_sizes[0] / (BB * FF);
    const int SMEM_BYTES = SM_FLOATS * 4;

    cudaFuncSetAttribute(lstm_ae_kernel,
                         cudaFuncAttributeMaxDynamicSharedMemorySize, SMEM_BYTES);

    transposeU_kernel<<<(H * C4 + 255) / 256, 256>>>(Ue, Ud);
    lstm_ae_kernel<<<(BB + MB - 1) / MB, NT, SMEM_BYTES>>>(x, We, be, Wd, bd, Wo, bo, out, T);
}

// round 9
// speedup vs baseline: 1.0062x; 1.0062x over previous
#include <cuda_runtime.h>

#define H   128
#define FF  8
#define C4  512
#define MB  14
#define NT  256
#define BB  2048
#define KH  64
#define HS  20     // hsm row stride (floats): 16B-aligned, 4-way store conflict
#define L2E 1.4426950408889634f

// U blocked as UG[k][j][gate] (float4 per (k,j)): coalesced LDG.128.
__device__ __align__(16) float g_UGe[H * C4];
__device__ __align__(16) float g_UGd[H * C4];

typedef unsigned long long u64;

__device__ __forceinline__ u64 dup2(float v) {
    u64 r; asm("mov.b64 %0, {%1, %1};" : "=l"(r) : "f"(v)); return r;
}
__device__ __forceinline__ u64 pack2(float lo, float hi) {
    u64 r; asm("mov.b64 %0, {%1, %2};" : "=l"(r) : "f"(lo), "f"(hi)); return r;
}
__device__ __forceinline__ void fma2(u64& d, u64 a, u64 b) {
    asm("fma.rn.f32x2 %0, %1, %2, %0;" : "+l"(d) : "l"(a), "l"(b));
}
__device__ __forceinline__ void add2(u64& d, u64 a) {
    asm("add.rn.f32x2 %0, %0, %1;" : "+l"(d) : "l"(a));
}
__device__ __forceinline__ void unpack2(u64 v, float& lo, float& hi) {
    asm("mov.b64 {%0, %1}, %2;" : "=f"(lo), "=f"(hi) : "l"(v));
}
__device__ __forceinline__ float ex2f(float x){ float r; asm("ex2.approx.f32 %0, %1;" : "=f"(r) : "f"(x)); return r; }
__device__ __forceinline__ float rcpf(float x){ float r; asm("rcp.approx.f32 %0, %1;" : "=f"(r) : "f"(x)); return r; }

#define BARSYNC() asm volatile("bar.sync 0;" ::: "memory")

// i/f/o sigmoids + g tanh for one row, one shared rcp per (i,f) and (g,o).
// Safe: |z| < ~20 here, so the products cannot overflow.
__device__ __forceinline__ void gates_row(float zi, float zf, float zg, float zo,
                                          float cin, float& cout, float& so) {
    float di = 1.f + ex2f(-L2E * zi);
    float df = 1.f + ex2f(-L2E * zf);
    float r  = rcpf(di * df);
    float si = r * df, sf = r * di;
    float dg = 1.f + ex2f(2.f * L2E * zg);
    float dd = 1.f + ex2f(-L2E * zo);
    float r2 = rcpf(dg * dd);
    float tg = fmaf(-2.f, r2 * dd, 1.f);
    so = r2 * dg;
    cout = fmaf(sf, cin, si * tg);
}

// 7 row-pairs from a stride-HS row (base 16B-aligned): 3x LDS.128 + 1x LDS.64
__device__ __forceinline__ void load_pairs7(u64* hp, const float* row) {
    ulonglong2 a = *(const ulonglong2*)(row);
    ulonglong2 b = *(const ulonglong2*)(row + 4);
    ulonglong2 c = *(const ulonglong2*)(row + 8);
    hp[0] = a.x; hp[1] = a.y; hp[2] = b.x; hp[3] = b.y;
    hp[4] = c.x; hp[5] = c.y;
    hp[6] = *(const u64*)(row + 12);
}

__global__ void transposeU_kernel(const float* __restrict__ Ue, const float* __restrict__ Ud) {
    int i = blockIdx.x * blockDim.x + threadIdx.x;
    if (i < H * C4) {
        int k = i / C4, c = i % C4;
        int o = (k * H + (c & 127)) * 4 + (c >> 7);
        g_UGe[o] = Ue[i];
        g_UGd[o] = Ud[i];
    }
}

// dyn smem (floats): hsm[2][128][HS] | xring[3][8][16] | ysm[8][16] | wsm | wosm | zex2
#define SM_H   0
#define SM_XR  5120
#define SM_Y   5504
#define SM_W   5632
#define SM_WO  9728
#define SM_ZX  10752
#define SM_FLOATS 17920

// Group G: k in [G*64, G*64+64). G0 keeps pairs 0-3 (rows 0-7) and the x
// prefetch/decoder head threads; G1 keeps pairs 4-6. Bias + x@W are folded
// into the keeper; only h@U partials of non-kept pairs cross via zex2.
template<int G>
__device__ __forceinline__ void lstm_body(
    int tid, int rs, int T,
    const float* __restrict__ x,
    const float* __restrict__ We, const float* __restrict__ be,
    const float* __restrict__ Wd, const float* __restrict__ bd,
    const float* __restrict__ bog,
    float* __restrict__ out,
    float* hsm, float* xring, float* ysm, float* wsm, const float* wosm,
    ulonglong2* zex2)
{
    constexpr int KK0 = G * KH;
    constexpr int P0  = G ? 4 : 0;            // kept pairs [P0, P0+NPk)
    constexpr int NPk = G ? 3 : 4;
    constexpr int W0  = G ? 0 : 4;            // crossing pairs [W0, W0+NPw)
    constexpr int NPw = G ? 4 : 3;

    const int j = tid & (H - 1);
    const int  xm = tid >> 3, xf = tid & 7;
    const bool xth = tid < MB * FF;           // G0-only helper threads
    const bool gx  = xth && (rs + xm < BB);
    const float bof = bog[xf];
    const float* xrow = x   + (size_t)(rs + xm) * T * FF + xf;
    float*       orow = out + (size_t)(rs + xm) * T * FF + xf;

    float cst[2 * NPk];
    #pragma unroll
    for (int i = 0; i < 2 * NPk; i++) cst[i] = 0.f;

    int buf = 0;

    for (int phase = 0; phase < 2; phase++) {
        const bool dec = (phase == 1);
        const float4* UG4j = ((const float4*)(dec ? g_UGd : g_UGe)) + j;
        const float*  Wm   = dec ? Wd : We;
        const float*  bv   = dec ? bd : be;

        for (int i = tid; i < FF * C4; i += NT) {      // stage W [f][j][g]
            int f = i >> 9, c = i & 511;
            wsm[(f * H + (c & 127)) * 4 + (c >> 7)] = Wm[i];
        }
        u64 bdv[4];
        #pragma unroll
        for (int g = 0; g < 4; g++) bdv[g] = dup2(bv[g * H + j]);
        if (dec && gx) ysm[xf * 16 + xm] = xrow[(size_t)(T - 1) * FF];  // y0 = x[:,T-1,:]
        BARSYNC();

        for (int t = 0; t < T; t++) {
            const int nbuf = buf ^ 1;
            const float* hbuf = hsm + buf  * (H * HS);
            float*       hnew = hsm + nbuf * (H * HS);

            if (dec) BARSYNC();               // BAR_A (decoder: before reading ysm)

            // ---- acc init + x@W for kept pairs ----
            u64 acc[4][7];
            #pragma unroll
            for (int g = 0; g < 4; g++)
                #pragma unroll
                for (int p = 0; p < 7; p++)
                    acc[g][p] = (p >= P0 && p < P0 + NPk) ? bdv[g] : 0ull;

            {
                const float* xb = dec ? ysm : (xring + (t % 3) * 128);
                #pragma unroll
                for (int f = 0; f < FF; f++) {
                    float4 wf4 = ((const float4*)wsm)[f * H + j];
                    u64 xp[NPk];
                    #pragma unroll
                    for (int pi = 0; pi < NPk; pi++)
                        xp[pi] = *(const u64*)(xb + f * 16 + 2 * (P0 + pi));
                    #pragma unroll
                    for (int g = 0; g < 4; g++) {
                        u64 wd = dup2(((const float*)&wf4)[g]);
                        #pragma unroll
                        for (int pi = 0; pi < NPk; pi++) fma2(acc[g][P0 + pi], xp[pi], wd);
                    }
                }
            }

            if (!dec) BARSYNC();              // BAR_A (encoder: h(t-1)/zex drained)

            // ---- h @ U over k in [KK0, KK0+64): 16 blocks of 4k, ring depth 2 ----
            float4 ur0[4], ur1[4];
            {
                const float4* u0p = UG4j + KK0 * H;
                #pragma unroll
                for (int q = 0; q < 4; q++) { ur0[q] = u0p[q * H]; ur1[q] = u0p[(4 + q) * H]; }
            }
            const float4* uld = UG4j + (KK0 + 8) * H;  // next block to load
            const float*  hq  = hbuf + KK0 * HS;

            #pragma unroll 1
            for (int kb2 = 0; kb2 < 7; kb2++) {
                // consume ur0 (block 2*kb2), reload it with block 2*kb2+2
                #pragma unroll
                for (int q = 0; q < 4; q++) {
                    u64 hp[7];
                    load_pairs7(hp, hq + q * HS);
                    #pragma unroll
                    for (int g = 0; g < 4; g++) {
                        u64 d = dup2(((const float*)&ur0[q])[g]);
                        #pragma unroll
                        for (int p = 0; p < 7; p++) fma2(acc[g][p], hp[p], d);
                    }
                }
                #pragma unroll
                for (int q = 0; q < 4; q++) ur0[q] = uld[q * H];
                hq += 4 * HS;
                // consume ur1 (block 2*kb2+1), reload it with block 2*kb2+3
                #pragma unroll
                for (int q = 0; q < 4; q++) {
                    u64 hp[7];
                    load_pairs7(hp, hq + q * HS);
                    #pragma unroll
                    for (int g = 0; g < 4; g++) {
                        u64 d = dup2(((const float*)&ur1[q])[g]);
                        #pragma unroll
                        for (int p = 0; p < 7; p++) fma2(acc[g][p], hp[p], d);
                    }
                }
                #pragma unroll
                for (int q = 0; q < 4; q++) ur1[q] = uld[(4 + q) * H];
                hq  += 4 * HS;
                uld += 8 * H;
            }
            #pragma unroll
            for (int kb = 0; kb < 2; kb++) {   // tail blocks 14 (ur0), 15 (ur1)
                #pragma unroll
                for (int q = 0; q < 4; q++) {
                    u64 hp[7];
                    load_pairs7(hp, hq + q * HS);
                    const float4& uu = kb ? ur1[q] : ur0[q];
                    #pragma unroll
                    for (int g = 0; g < 4; g++) {
                        u64 d = dup2(((const float*)&uu)[g]);
                        #pragma unroll
                        for (int p = 0; p < 7; p++) fma2(acc[g][p], hp[p], d);
                    }
                }
                hq += 4 * HS;
            }

            // ---- cross non-kept h@U partials (2 gates per STS.128) ----
            #pragma unroll
            for (int pi = 0; pi < NPw; pi++) {
                const int p = W0 + pi;
                #pragma unroll
                for (int g2 = 0; g2 < 2; g2++) {
                    ulonglong2 v;
                    v.x = acc[2 * g2][p];
                    v.y = acc[2 * g2 + 1][p];
                    zex2[(g2 * 7 + p) * H + j] = v;
                }
            }
            BARSYNC();                         // BAR_B: zex ready

            // ---- gather + gates for kept pairs -> write h into other buffer ----
            u64* hrow = (u64*)(hnew + j * HS);
            #pragma unroll
            for (int pi = 0; pi < NPk; pi++) {
                const int p = P0 + pi;
                ulonglong2 e0 = zex2[(0 * 7 + p) * H + j];
                ulonglong2 e1 = zex2[(1 * 7 + p) * H + j];
                add2(acc[0][p], e0.x); add2(acc[1][p], e0.y);
                add2(acc[2][p], e1.x); add2(acc[3][p], e1.y);
                float zi0, zi1, zf0, zf1, zg0, zg1, zo0, zo1;
                unpack2(acc[0][p], zi0, zi1);
                unpack2(acc[1][p], zf0, zf1);
                unpack2(acc[2][p], zg0, zg1);
                unpack2(acc[3][p], zo0, zo1);
                float c0, c1, so0, so1;
                gates_row(zi0, zf0, zg0, zo0, cst[2 * pi    ], c0, so0);
                gates_row(zi1, zf1, zg1, zo1, cst[2 * pi + 1], c1, so1);
                cst[2 * pi    ] = c0;
                cst[2 * pi + 1] = c1;
                float dc0 = 1.f + ex2f(2.f * L2E * c0);
                float dc1 = 1.f + ex2f(2.f * L2E * c1);
                float rc  = rcpf(dc0 * dc1);
                float h0  = so0 * fmaf(-2.f, rc * dc1, 1.f);
                float h1  = so1 * fmaf(-2.f, rc * dc0, 1.f);
                hrow[p] = pack2(h0, h1);
            }

            if (!dec) {
                // prefetch x(t+2) into ring slot (t+2)%3 (read two steps later)
                if (G == 0 && gx && t + 2 < T)
                    (xring + ((t + 2) % 3) * 128)[xf * 16 + xm] = xrow[(size_t)(t + 2) * FF];
            } else {
                BARSYNC();                     // BAR_C: h(t) complete
                if (xth) {
                    float a = 0.f, b2 = 0.f, c2 = 0.f, d2 = 0.f;
                    #pragma unroll 8
                    for (int k = 0; k < H; k += 4) {
                        a  = fmaf(hnew[(k    ) * HS + xm], wosm[(k    ) * FF + xf], a);
                        b2 = fmaf(hnew[(k + 1) * HS + xm], wosm[(k + 1) * FF + xf], b2);
                        c2 = fmaf(hnew[(k + 2) * HS + xm], wosm[(k + 2) * FF + xf], c2);
                        d2 = fmaf(hnew[(k + 3) * HS + xm], wosm[(k + 3) * FF + xf], d2);
                    }
                    float y = fmaxf(bof + ((a + b2) + (c2 + d2)), 0.f);
                    ysm[xf * 16 + xm] = y;
                    if (gx) orow[(size_t)t * FF] = y;
                }
            }
            buf = nbuf;
        }
    }
}

__global__ void __launch_bounds__(NT, 1)
lstm_ae_kernel(const float* __restrict__ x,
               const float* __restrict__ We, const float* __restrict__ be,
               const float* __restrict__ Wd, const float* __restrict__ bd,
               const float* __restrict__ Wo, const float* __restrict__ bog,
               float* __restrict__ out, int T)
{
    extern __shared__ __align__(16) float sm[];
    float*       hsm   = sm + SM_H;
    float*       xring = sm + SM_XR;
    float*       ysm   = sm + SM_Y;
    float*       wsm   = sm + SM_W;
    float*       wosm  = sm + SM_WO;
    ulonglong2*  zex2  = (ulonglong2*)(sm + SM_ZX);

    const int tid = threadIdx.x;
    const int rs  = blockIdx.x * MB;

    for (int i = tid; i < SM_W; i += NT) sm[i] = 0.f;       // hsm + xring + ysm
    for (int i = tid; i < H * FF; i += NT) wosm[i] = Wo[i];
    {   // prefill ring slots for t = 0, 1
        const int xm = tid >> 3, xf = tid & 7;
        if (tid < MB * FF && rs + xm < BB) {
            const float* xr = x + (size_t)(rs + xm) * T * FF + xf;
            xring[0 * 128 + xf * 16 + xm] = xr[0];
            xring[1 * 128 + xf * 16 + xm] = xr[FF];
        }
    }
    __syncthreads();

    if (tid < 128)
        lstm_body<0>(tid, rs, T, x, We, be, Wd, bd, bog, out, hsm, xring, ysm, wsm, wosm, zex2);
    else
        lstm_body<1>(tid, rs, T, x, We, be, Wd, bd, bog, out, hsm, xring, ysm, wsm, wosm, zex2);
}

extern "C" void kernel_launch(void* const* d_in, const int* in_sizes, int n_in,
                              void* d_out, int out_size)
{
    const float* x  = (const float*)d_in[0];
    const float* We = (const float*)d_in[1];
    const float* Ue = (const float*)d_in[2];
    const float* be = (const float*)d_in[3];
    const float* Wd = (const float*)d_in[4];
    const float* Ud = (const float*)d_in[5];
    const float* bd = (const float*)d_in[6];
    const float* Wo = (const float*)d_in[7];
    const float* bo = (const float*)d_in[8];
    float* out = (float*)d_out;

    const int T = in_sizes[0] / (BB * FF);
    const int SMEM_BYTES = SM_FLOATS * 4;

    cudaFuncSetAttribute(lstm_ae_kernel,
                         cudaFuncAttributeMaxDynamicSharedMemorySize, SMEM_BYTES);

    transposeU_kernel<<<(H * C4 + 255) / 256, 256>>>(Ue, Ud);
    lstm_ae_kernel<<<(BB + MB - 1) / MB, NT, SMEM_BYTES>>>(x, We, be, Wd, bd, Wo, bo, out, T);
}

// round 10
// speedup vs baseline: 1.0070x; 1.0008x over previous
#include <cuda_runtime.h>

#define H   128
#define FF  8
#define C4  512
#define MB  14
#define NT  256
#define BB  2048
#define KH  64
#define HS  20     // hsm row stride (floats): 16B-aligned, 4-way store conflict
#define L2E 1.4426950408889634f

// U blocked as UG[k][j][gate] (float4 per (k,j)): coalesced LDG.128.
__device__ __align__(16) float g_UGe[H * C4];
__device__ __align__(16) float g_UGd[H * C4];

typedef unsigned long long u64;

__device__ __forceinline__ u64 dup2(float v) {
    u64 r; asm("mov.b64 %0, {%1, %1};" : "=l"(r) : "f"(v)); return r;
}
__device__ __forceinline__ u64 pack2(float lo, float hi) {
    u64 r; asm("mov.b64 %0, {%1, %2};" : "=l"(r) : "f"(lo), "f"(hi)); return r;
}
__device__ __forceinline__ void fma2(u64& d, u64 a, u64 b) {
    asm("fma.rn.f32x2 %0, %1, %2, %0;" : "+l"(d) : "l"(a), "l"(b));
}
__device__ __forceinline__ void add2(u64& d, u64 a) {
    asm("add.rn.f32x2 %0, %0, %1;" : "+l"(d) : "l"(a));
}
__device__ __forceinline__ void unpack2(u64 v, float& lo, float& hi) {
    asm("mov.b64 {%0, %1}, %2;" : "=f"(lo), "=f"(hi) : "l"(v));
}
__device__ __forceinline__ float ex2f(float x){ float r; asm("ex2.approx.f32 %0, %1;" : "=f"(r) : "f"(x)); return r; }
__device__ __forceinline__ float rcpf(float x){ float r; asm("rcp.approx.f32 %0, %1;" : "=f"(r) : "f"(x)); return r; }

#define BARSYNC() asm volatile("bar.sync 0;" ::: "memory")

// i/f/o sigmoids + g tanh for one row, one shared rcp per (i,f) and (g,o).
// Safe: |z| < ~20 here, so the products cannot overflow.
__device__ __forceinline__ void gates_row(float zi, float zf, float zg, float zo,
                                          float cin, float& cout, float& so) {
    float di = 1.f + ex2f(-L2E * zi);
    float df = 1.f + ex2f(-L2E * zf);
    float r  = rcpf(di * df);
    float si = r * df, sf = r * di;
    float dg = 1.f + ex2f(2.f * L2E * zg);
    float dd = 1.f + ex2f(-L2E * zo);
    float r2 = rcpf(dg * dd);
    float tg = fmaf(-2.f, r2 * dd, 1.f);
    so = r2 * dg;
    cout = fmaf(sf, cin, si * tg);
}

// 7 row-pairs from a stride-HS row (base 16B-aligned): 3x LDS.128 + 1x LDS.64
__device__ __forceinline__ void load_pairs7(u64* hp, const float* row) {
    ulonglong2 a = *(const ulonglong2*)(row);
    ulonglong2 b = *(const ulonglong2*)(row + 4);
    ulonglong2 c = *(const ulonglong2*)(row + 8);
    hp[0] = a.x; hp[1] = a.y; hp[2] = b.x; hp[3] = b.y;
    hp[4] = c.x; hp[5] = c.y;
    hp[6] = *(const u64*)(row + 12);
}

__global__ void transposeU_kernel(const float* __restrict__ Ue, const float* __restrict__ Ud) {
    int i = blockIdx.x * blockDim.x + threadIdx.x;
    if (i < H * C4) {
        int k = i / C4, c = i % C4;
        int o = (k * H + (c & 127)) * 4 + (c >> 7);
        g_UGe[o] = Ue[i];
        g_UGd[o] = Ud[i];
    }
}

// dyn smem (floats): hsm[2][128][HS] | xring[3][8][16] | ysm[8][16] | wsm | wosm | zex2
#define SM_H   0
#define SM_XR  5120
#define SM_Y   5504
#define SM_W   5632
#define SM_WO  9728
#define SM_ZX  10752
#define SM_FLOATS 17920

// Group G: k in [G*64, G*64+64). G0 keeps pairs 0-3 (rows 0-7) and the x
// prefetch/decoder head threads; G1 keeps pairs 4-6. Bias + x@W are folded
// into the keeper; only h@U partials of non-kept pairs cross via zex2.
template<int G>
__device__ __forceinline__ void lstm_body(
    int tid, int rs, int T,
    const float* __restrict__ x,
    const float* __restrict__ We, const float* __restrict__ be,
    const float* __restrict__ Wd, const float* __restrict__ bd,
    const float* __restrict__ bog,
    float* __restrict__ out,
    float* hsm, float* xring, float* ysm, float* wsm, const float* wosm,
    ulonglong2* zex2)
{
    constexpr int KK0 = G * KH;
    constexpr int P0  = G ? 4 : 0;            // kept pairs [P0, P0+NPk)
    constexpr int NPk = G ? 3 : 4;
    constexpr int W0  = G ? 0 : 4;            // crossing pairs [W0, W0+NPw)
    constexpr int NPw = G ? 4 : 3;

    const int j = tid & (H - 1);
    const int  xm = tid >> 3, xf = tid & 7;
    const bool xth = tid < MB * FF;           // G0-only helper threads
    const bool gx  = xth && (rs + xm < BB);
    const float bof = bog[xf];
    const float* xrow = x   + (size_t)(rs + xm) * T * FF + xf;
    float*       orow = out + (size_t)(rs + xm) * T * FF + xf;

    float cst[2 * NPk];
    #pragma unroll
    for (int i = 0; i < 2 * NPk; i++) cst[i] = 0.f;

    int buf = 0;

    for (int phase = 0; phase < 2; phase++) {
        const bool dec = (phase == 1);
        const float4* UG4j = ((const float4*)(dec ? g_UGd : g_UGe)) + j;
        const float*  Wm   = dec ? Wd : We;
        const float*  bv   = dec ? bd : be;

        for (int i = tid; i < FF * C4; i += NT) {      // stage W [f][j][g]
            int f = i >> 9, c = i & 511;
            wsm[(f * H + (c & 127)) * 4 + (c >> 7)] = Wm[i];
        }
        u64 bdv[4];
        #pragma unroll
        for (int g = 0; g < 4; g++) bdv[g] = dup2(bv[g * H + j]);
        if (dec && gx) ysm[xf * 16 + xm] = xrow[(size_t)(T - 1) * FF];  // y0 = x[:,T-1,:]
        BARSYNC();

        for (int t = 0; t < T; t++) {
            const int nbuf = buf ^ 1;
            const float* hbuf = hsm + buf  * (H * HS);
            float*       hnew = hsm + nbuf * (H * HS);

            if (dec) BARSYNC();               // BAR_A (decoder: before reading ysm)

            // ---- acc init + x@W for kept pairs ----
            u64 acc[4][7];
            #pragma unroll
            for (int g = 0; g < 4; g++)
                #pragma unroll
                for (int p = 0; p < 7; p++)
                    acc[g][p] = (p >= P0 && p < P0 + NPk) ? bdv[g] : 0ull;

            {
                const float* xb = dec ? ysm : (xring + (t % 3) * 128);
                #pragma unroll
                for (int f = 0; f < FF; f++) {
                    float4 wf4 = ((const float4*)wsm)[f * H + j];
                    u64 xp[NPk];
                    #pragma unroll
                    for (int pi = 0; pi < NPk; pi++)
                        xp[pi] = *(const u64*)(xb + f * 16 + 2 * (P0 + pi));
                    #pragma unroll
                    for (int g = 0; g < 4; g++) {
                        u64 wd = dup2(((const float*)&wf4)[g]);
                        #pragma unroll
                        for (int pi = 0; pi < NPk; pi++) fma2(acc[g][P0 + pi], xp[pi], wd);
                    }
                }
            }

            if (!dec) BARSYNC();              // BAR_A (encoder: h(t-1)/zex drained)

            // ---- h @ U over k in [KK0, KK0+64): 16 blocks of 4k, ring depth 2 ----
            float4 ur0[4], ur1[4];
            {
                const float4* u0p = UG4j + KK0 * H;
                #pragma unroll
                for (int q = 0; q < 4; q++) { ur0[q] = u0p[q * H]; ur1[q] = u0p[(4 + q) * H]; }
            }
            const float4* uld = UG4j + (KK0 + 8) * H;  // next block to load
            const float*  hq  = hbuf + KK0 * HS;

            #pragma unroll 1
            for (int kb2 = 0; kb2 < 7; kb2++) {
                // consume ur0 (block 2*kb2), reload it with block 2*kb2+2
                #pragma unroll
                for (int q = 0; q < 4; q++) {
                    u64 hp[7];
                    load_pairs7(hp, hq + q * HS);
                    #pragma unroll
                    for (int g = 0; g < 4; g++) {
                        u64 d = dup2(((const float*)&ur0[q])[g]);
                        #pragma unroll
                        for (int p = 0; p < 7; p++) fma2(acc[g][p], hp[p], d);
                    }
                }
                #pragma unroll
                for (int q = 0; q < 4; q++) ur0[q] = uld[q * H];
                hq += 4 * HS;
                // consume ur1 (block 2*kb2+1), reload it with block 2*kb2+3
                #pragma unroll
                for (int q = 0; q < 4; q++) {
                    u64 hp[7];
                    load_pairs7(hp, hq + q * HS);
                    #pragma unroll
                    for (int g = 0; g < 4; g++) {
                        u64 d = dup2(((const float*)&ur1[q])[g]);
                        #pragma unroll
                        for (int p = 0; p < 7; p++) fma2(acc[g][p], hp[p], d);
                    }
                }
                #pragma unroll
                for (int q = 0; q < 4; q++) ur1[q] = uld[(4 + q) * H];
                hq  += 4 * HS;
                uld += 8 * H;
            }
            #pragma unroll
            for (int kb = 0; kb < 2; kb++) {   // tail blocks 14 (ur0), 15 (ur1)
                #pragma unroll
                for (int q = 0; q < 4; q++) {
                    u64 hp[7];
                    load_pairs7(hp, hq + q * HS);
                    const float4& uu = kb ? ur1[q] : ur0[q];
                    #pragma unroll
                    for (int g = 0; g < 4; g++) {
                        u64 d = dup2(((const float*)&uu)[g]);
                        #pragma unroll
                        for (int p = 0; p < 7; p++) fma2(acc[g][p], hp[p], d);
                    }
                }
                hq += 4 * HS;
            }

            // ---- cross non-kept h@U partials (2 gates per STS.128) ----
            #pragma unroll
            for (int pi = 0; pi < NPw; pi++) {
                const int p = W0 + pi;
                #pragma unroll
                for (int g2 = 0; g2 < 2; g2++) {
                    ulonglong2 v;
                    v.x = acc[2 * g2][p];
                    v.y = acc[2 * g2 + 1][p];
                    zex2[(g2 * 7 + p) * H + j] = v;
                }
            }
            BARSYNC();                         // BAR_B: zex ready

            // ---- gather + gates for kept pairs -> write h into other buffer ----
            u64* hrow = (u64*)(hnew + j * HS);
            #pragma unroll
            for (int pi = 0; pi < NPk; pi++) {
                const int p = P0 + pi;
                ulonglong2 e0 = zex2[(0 * 7 + p) * H + j];
                ulonglong2 e1 = zex2[(1 * 7 + p) * H + j];
                add2(acc[0][p], e0.x); add2(acc[1][p], e0.y);
                add2(acc[2][p], e1.x); add2(acc[3][p], e1.y);
                float zi0, zi1, zf0, zf1, zg0, zg1, zo0, zo1;
                unpack2(acc[0][p], zi0, zi1);
                unpack2(acc[1][p], zf0, zf1);
                unpack2(acc[2][p], zg0, zg1);
                unpack2(acc[3][p], zo0, zo1);
                float c0, c1, so0, so1;
                gates_row(zi0, zf0, zg0, zo0, cst[2 * pi    ], c0, so0);
                gates_row(zi1, zf1, zg1, zo1, cst[2 * pi + 1], c1, so1);
                cst[2 * pi    ] = c0;
                cst[2 * pi + 1] = c1;
                float dc0 = 1.f + ex2f(2.f * L2E * c0);
                float dc1 = 1.f + ex2f(2.f * L2E * c1);
                float rc  = rcpf(dc0 * dc1);
                float h0  = so0 * fmaf(-2.f, rc * dc1, 1.f);
                float h1  = so1 * fmaf(-2.f, rc * dc0, 1.f);
                hrow[p] = pack2(h0, h1);
            }

            if (!dec) {
                // prefetch x(t+2) into ring slot (t+2)%3 (read two steps later)
                if (G == 0 && gx && t + 2 < T)
                    (xring + ((t + 2) % 3) * 128)[xf * 16 + xm] = xrow[(size_t)(t + 2) * FF];
            } else {
                BARSYNC();                     // BAR_C: h(t) complete
                if (xth) {
                    float a = 0.f, b2 = 0.f, c2 = 0.f, d2 = 0.f;
                    #pragma unroll 8
                    for (int k = 0; k < H; k += 4) {
                        a  = fmaf(hnew[(k    ) * HS + xm], wosm[(k    ) * FF + xf], a);
                        b2 = fmaf(hnew[(k + 1) * HS + xm], wosm[(k + 1) * FF + xf], b2);
                        c2 = fmaf(hnew[(k + 2) * HS + xm], wosm[(k + 2) * FF + xf], c2);
                        d2 = fmaf(hnew[(k + 3) * HS + xm], wosm[(k + 3) * FF + xf], d2);
                    }
                    float y = fmaxf(bof + ((a + b2) + (c2 + d2)), 0.f);
                    ysm[xf * 16 + xm] = y;
                    if (gx) orow[(size_t)t * FF] = y;
                }
            }
            buf = nbuf;
        }
    }
}

__global__ void __launch_bounds__(NT, 1)
lstm_ae_kernel(const float* __restrict__ x,
               const float* __restrict__ We, const float* __restrict__ be,
               const float* __restrict__ Wd, const float* __restrict__ bd,
               const float* __restrict__ Wo, const float* __restrict__ bog,
               float* __restrict__ out, int T)
{
    extern __shared__ __align__(16) float sm[];
    float*       hsm   = sm + SM_H;
    float*       xring = sm + SM_XR;
    float*       ysm   = sm + SM_Y;
    float*       wsm   = sm + SM_W;
    float*       wosm  = sm + SM_WO;
    ulonglong2*  zex2  = (ulonglong2*)(sm + SM_ZX);

    const int tid = threadIdx.x;
    const int rs  = blockIdx.x * MB;

    for (int i = tid; i < SM_W; i += NT) sm[i] = 0.f;       // hsm + xring + ysm
    for (int i = tid; i < H * FF; i += NT) wosm[i] = Wo[i];
    {   // prefill ring slots for t = 0, 1
        const int xm = tid >> 3, xf = tid & 7;
        if (tid < MB * FF && rs + xm < BB) {
            const float* xr = x + (size_t)(rs + xm) * T * FF + xf;
            xring[0 * 128 + xf * 16 + xm] = xr[0];
            xring[1 * 128 + xf * 16 + xm] = xr[FF];
        }
    }
    __syncthreads();

    if (tid < 128)
        lstm_body<0>(tid, rs, T, x, We, be, Wd, bd, bog, out, hsm, xring, ysm, wsm, wosm, zex2);
    else
        lstm_body<1>(tid, rs, T, x, We, be, Wd, bd, bog, out, hsm, xring, ysm, wsm, wosm, zex2);
}

extern "C" void kernel_launch(void* const* d_in, const int* in_sizes, int n_in,
                              void* d_out, int out_size)
{
    const float* x  = (const float*)d_in[0];
    const float* We = (const float*)d_in[1];
    const float* Ue = (const float*)d_in[2];
    const float* be = (const float*)d_in[3];
    const float* Wd = (const float*)d_in[4];
    const float* Ud = (const float*)d_in[5];
    const float* bd = (const float*)d_in[6];
    const float* Wo = (const float*)d_in[7];
    const float* bo = (const float*)d_in[8];
    float* out = (float*)d_out;

    const int T = in_sizes[0] / (BB * FF);
    const int SMEM_BYTES = SM_FLOATS * 4;

    cudaFuncSetAttribute(lstm_ae_kernel,
                         cudaFuncAttributeMaxDynamicSharedMemorySize, SMEM_BYTES);

    transposeU_kernel<<<(H * C4 + 255) / 256, 256>>>(Ue, Ud);
    lstm_ae_kernel<<<(BB + MB - 1) / MB, NT, SMEM_BYTES>>>(x, We, be, Wd, bd, Wo, bo, out, T);
}